// round 13
// baseline (speedup 1.0000x reference)
#include <cuda_runtime.h>

// Problem constants (fixed by the reference)
#define BB 16
#define CC 3
#define TT 16
#define HH 224
#define WW 224
#define W4 (WW / 4)                     // 56 float4 per row
#define PLANE4 (HH * W4)                // 12544 float4 per (b,c,t) plane
#define COLOR_STRENGTH 0.3f
#define NOISE_STRENGTH 0.02f
#define DROPOUT_PROB 0.05f
#define HFLIP_PROB 0.5f
#define MAX_JITTER 3

#define THREADS 256
#define ILP 4
#define BLK_ELEMS (THREADS * ILP)       // 1024 float4 per block
#define GRID_X ((PLANE4 + BLK_ELEMS - 1) / BLK_ELEMS)  // 13 (last block partial)

__device__ __forceinline__ float clamp01(float x) {
    return fminf(fmaxf(x, 0.0f), 1.0f);
}

__device__ __forceinline__ float aug_one(float v, float n, float bf, float cf) {
    float x = clamp01(v * bf);                     // brightness
    x = clamp01((x - 0.5f) * cf + 0.5f);           // contrast
    x = clamp01(x + n * NOISE_STRENGTH);           // noise
    return x;
}

__global__ void __launch_bounds__(THREADS)
augment_fused(const float4* __restrict__ video,
              const float4* __restrict__ noise,
              float4* __restrict__ out,
              const int*   __restrict__ jitter,
              const float* __restrict__ b_rand,
              const float* __restrict__ c_rand,
              const float* __restrict__ flip_rand,
              const float* __restrict__ drop_rand) {
    // blockIdx.y encodes (b, c, t); all divisors compile-time constants.
    const int bct = blockIdx.y;                 // [0, 768)
    const int t   = bct % TT;
    const int bc  = bct / TT;                   // b*CC + c
    const int b   = bc / CC;

    // ---- block-uniform per-batch params (broadcast L1 loads) ----
    const float bf   = 1.0f + (b_rand[b] - 0.5f) * 2.0f * COLOR_STRENGTH;
    float cf         = 1.0f + (c_rand[b] - 0.5f) * 2.0f * COLOR_STRENGTH;
    cf = fminf(fmaxf(cf, 0.1f), 3.0f);
    const bool flip  = flip_rand[b] < HFLIP_PROB;
    const int  j     = jitter[b] - MAX_JITTER;  // [-3, 3]
    const int  tsrc  = (t - j + TT) & (TT - 1); // roll source frame

    bool kp = drop_rand[b * TT + t] > DROPOUT_PROB;
    if (t == 0 && !kp) {
        // guarantee >=1 kept frame: if nothing kept, frame 0 is kept
        bool any = false;
        #pragma unroll
        for (int t2 = 1; t2 < TT; ++t2)
            any |= (drop_rand[b * TT + t2] > DROPOUT_PROB);
        kp = !any;
    }

    const int base  = blockIdx.x * BLK_ELEMS + threadIdx.x;
    const int obase = bct * PLANE4;

    if (!kp) {
        // dropped frame: no reads, store zeros (block-uniform branch)
        #pragma unroll
        for (int u = 0; u < ILP; ++u) {
            int ip = base + u * THREADS;
            if (ip < PLANE4)
                out[obase + ip] = make_float4(0.0f, 0.0f, 0.0f, 0.0f);
        }
        return;
    }

    const int vplane = (bc * TT + tsrc) * PLANE4;

    // gather phase: front-batch all loads before any math (MLP = 2*ILP)
    int  ips[ILP];
    int  sidx[ILP];
    bool ok[ILP];
    float4 v[ILP], n[ILP];

    #pragma unroll
    for (int u = 0; u < ILP; ++u) {
        int ip = base + u * THREADS;
        ips[u] = ip;
        ok[u]  = ip < PLANE4;
        int h  = ip / W4;
        int w4 = ip - h * W4;
        int ws = flip ? (W4 - 1 - w4) : w4;
        sidx[u] = h * W4 + ws;
        if (ok[u]) v[u] = video[vplane + sidx[u]];
    }
    #pragma unroll
    for (int u = 0; u < ILP; ++u) {
        if (ok[u]) n[u] = noise[obase + sidx[u]];
    }

    #pragma unroll
    for (int u = 0; u < ILP; ++u) {
        if (!ok[u]) continue;
        float4 vv = v[u], nn = n[u];
        if (flip) {
            float tmp;
            tmp = vv.x; vv.x = vv.w; vv.w = tmp;
            tmp = vv.y; vv.y = vv.z; vv.z = tmp;
            tmp = nn.x; nn.x = nn.w; nn.w = tmp;
            tmp = nn.y; nn.y = nn.z; nn.z = tmp;
        }
        float4 o;
        o.x = aug_one(vv.x, nn.x, bf, cf);
        o.y = aug_one(vv.y, nn.y, bf, cf);
        o.z = aug_one(vv.z, nn.z, bf, cf);
        o.w = aug_one(vv.w, nn.w, bf, cf);
        out[obase + ips[u]] = o;
    }
}

extern "C" void kernel_launch(void* const* d_in, const int* in_sizes, int n_in,
                              void* d_out, int out_size) {
    // metadata order: video, jitter, b_rand, c_rand, noise, flip_rand, drop_rand
    const float* video     = (const float*)d_in[0];
    const int*   jitter    = (const int*)d_in[1];
    const float* b_rand    = (const float*)d_in[2];
    const float* c_rand    = (const float*)d_in[3];
    const float* noise     = (const float*)d_in[4];
    const float* flip_rand = (const float*)d_in[5];
    const float* drop_rand = (const float*)d_in[6];
    float* out = (float*)d_out;

    dim3 grid(GRID_X, BB * CC * TT);   // (13, 768)
    augment_fused<<<grid, THREADS>>>((const float4*)video,
                                     (const float4*)noise,
                                     (float4*)out,
                                     jitter, b_rand, c_rand, flip_rand, drop_rand);
}